// round 4
// baseline (speedup 1.0000x reference)
#include <cuda_runtime.h>
#include <cuda_bf16.h>
#include <cstdint>

// Problem constants (shapes fixed by setup_inputs)
#define BSZ   4
#define LSZ   2048
#define KNB   30      // TOP_K
#define NRBF  16
#define NF    272     // 16 positional + 16 banks * 16 rbf
#define NOUT  128
#define MAXREL 32

// -------- device scratch (no cudaMalloc allowed) --------
__device__ float g_Cb  [BSZ*LSZ*3];
__device__ int   g_Eidx[BSZ*LSZ*KNB];
__device__ float g_Dsel[BSZ*LSZ*KNB];

// pair tables: dist(A_atom of residue i, B_atom of residue j)
// atom codes: 0=N (X[...,0]), 1=C (X[...,1]), 2=Ca (X[...,2]), 3=Cb (virtual)
__constant__ int c_PA[15] = {0,2,3,1,1,1,0,0,3,0,2,3,2,3,2};
__constant__ int c_PB[15] = {0,2,3,0,2,3,2,3,2,1,1,1,0,0,3};

// ============================================================
// Kernel 1: virtual C-beta per residue
// ============================================================
__global__ void cb_kernel(const float* __restrict__ X)
{
    int i = blockIdx.x * 256 + threadIdx.x;
    if (i >= BSZ*LSZ) return;
    const float* x = &X[i*12];
    float Nx=x[0],  Ny=x[1],  Nz=x[2];   // N  = X[:,:,0]
    float Cx=x[3],  Cy=x[4],  Cz=x[5];   // C  = X[:,:,1]
    float Ax=x[6],  Ay=x[7],  Az=x[8];   // Ca = X[:,:,2]
    float bx=Ax-Nx, by=Ay-Ny, bz=Az-Nz;          // b = Ca - N
    float cx=Cx-Ax, cy=Cy-Ay, cz=Cz-Az;          // c = C - Ca
    float ax = by*cz - bz*cy;                    // a = cross(b,c)
    float ay = bz*cx - bx*cz;
    float az = bx*cy - by*cx;
    g_Cb[i*3+0] = -0.58273431f*ax + 0.56802827f*bx - 0.54067466f*cx + Ax;
    g_Cb[i*3+1] = -0.58273431f*ay + 0.56802827f*by - 0.54067466f*cy + Ay;
    g_Cb[i*3+2] = -0.58273431f*az + 0.56802827f*bz - 0.54067466f*cz + Az;
}

// ============================================================
// Kernel 2: masked pairwise C-C distances + exact top-30
// key = (float_bits << 32) | j  -> min gives ascending distance,
// ties broken by lower index == jax.lax.top_k stable order.
// ============================================================
__global__ __launch_bounds__(256) void topk_kernel(
    const float* __restrict__ X, const float* __restrict__ mask,
    float* __restrict__ outIdxF)
{
    int row = blockIdx.x;           // b*L + i
    int b   = row / LSZ;
    int t   = threadIdx.x;

    __shared__ float sD[LSZ];
    __shared__ float wmax[8];
    __shared__ unsigned long long wmin[8];
    __shared__ float sDmax;

    float cx = X[row*12+3], cy = X[row*12+4], cz = X[row*12+5];  // C atom
    float mi = mask[row];

    float lmax = 0.f;
    for (int j = t; j < LSZ; j += 256) {
        const float* xj = &X[(b*LSZ + j)*12 + 3];
        float dx = cx-xj[0], dy = cy-xj[1], dz = cz-xj[2];
        float d  = sqrtf(dx*dx + dy*dy + dz*dz + 1e-6f);
        float md = mi * mask[b*LSZ + j] * d;
        sD[j] = md;
        lmax = fmaxf(lmax, md);
    }
    #pragma unroll
    for (int o = 16; o > 0; o >>= 1) lmax = fmaxf(lmax, __shfl_xor_sync(0xffffffffu, lmax, o));
    if ((t & 31) == 0) wmax[t >> 5] = lmax;
    __syncthreads();
    if (t == 0) {
        float m = wmax[0];
        for (int w = 1; w < 8; w++) m = fmaxf(m, wmax[w]);
        sDmax = m;
    }
    __syncthreads();
    float Dmax = sDmax;
    for (int j = t; j < LSZ; j += 256) {
        float m2 = mi * mask[b*LSZ + j];
        sD[j] += (1.0f - m2) * Dmax;     // D_adjust
    }
    __syncthreads();

    for (int it = 0; it < KNB; it++) {
        unsigned long long best = ~0ull;
        #pragma unroll
        for (int r = 0; r < LSZ/256; r++) {
            int j = t + r*256;
            unsigned long long key =
                ((unsigned long long)__float_as_uint(sD[j]) << 32) | (unsigned)j;
            if (key < best) best = key;
        }
        #pragma unroll
        for (int o = 16; o > 0; o >>= 1) {
            unsigned long long oth = __shfl_xor_sync(0xffffffffu, best, o);
            if (oth < best) best = oth;
        }
        if ((t & 31) == 0) wmin[t >> 5] = best;
        __syncthreads();
        if (t == 0) {
            unsigned long long g = wmin[0];
            for (int w = 1; w < 8; w++) if (wmin[w] < g) g = wmin[w];
            int jm = (int)(unsigned)g;
            g_Eidx[row*KNB + it] = jm;
            g_Dsel[row*KNB + it] = __uint_as_float((unsigned)(g >> 32));
            if (outIdxF) outIdxF[row*KNB + it] = (float)jm;
            sD[jm] = __int_as_float(0x7f800000);   // +inf, remove from pool
        }
        __syncthreads();
    }
}

// ============================================================
// Kernel 3: fused edge features (positional + 16 RBF banks)
//           -> 272x128 projection -> layernorm
// One block per (b,i) row; 128 threads = one output column each,
// acc[30] register tile over the 30 neighbors.
// ============================================================
__global__ __launch_bounds__(128, 4) void edge_kernel(
    const float* __restrict__ X,
    const int*   __restrict__ ridx,
    const int*   __restrict__ chain,
    const float* __restrict__ W_pos,
    const float* __restrict__ b_pos,
    const float* __restrict__ W_edge,
    const float* __restrict__ gamma,
    const float* __restrict__ beta,
    float*       __restrict__ outE)
{
    int row = blockIdx.x;           // b*L + i
    int b   = row / LSZ;
    int t   = threadIdx.x;

    __shared__ float Fsm[KNB][NF];        // 30 x 272 feature tile
    __shared__ float ia[4][3];            // i atoms: N,C,Ca,Cb
    __shared__ float ja[KNB][4][3];       // j atoms per neighbor
    __shared__ int   jidx[KNB];
    __shared__ float dsel[KNB];
    __shared__ float dist[KNB][15];
    __shared__ float psum[4][KNB];
    __shared__ float psq [4][KNB];

    // stage neighbor list + i atoms
    if (t < KNB) { jidx[t] = g_Eidx[row*KNB + t]; dsel[t] = g_Dsel[row*KNB + t]; }
    if (t >= 32 && t < 41) { int r = t - 32; ia[r/3][r%3] = X[row*12 + r]; }
    if (t >= 64 && t < 67) { ia[3][t-64] = g_Cb[row*3 + (t-64)]; }
    __syncthreads();

    // stage j atoms (N,C,Ca from X; Cb virtual)
    for (int s = t; s < KNB*12; s += 128) {
        int k = s / 12, r = s % 12;
        int j = jidx[k];
        if (r < 9) ja[k][r/3][r%3] = X[(b*LSZ + j)*12 + r];
        else       ja[k][3][r-9]   = g_Cb[(b*LSZ + j)*3 + (r-9)];
    }

    // positional features: Fsm[k][0..15] = W_pos[d] + b_pos
    int my_ri = ridx[row];
    int my_ch = chain[row];
    for (int s = t; s < KNB*16; s += 128) {
        int k = s >> 4, f = s & 15;
        int j = jidx[k];
        int off  = my_ri - ridx[b*LSZ + j];
        int same = (my_ch == chain[b*LSZ + j]);
        int dcode = same ? min(max(off + MAXREL, 0), 2*MAXREL) : (2*MAXREL + 1);
        Fsm[k][f] = W_pos[dcode*16 + f] + b_pos[f];
    }
    __syncthreads();

    // 15 pair distances per edge
    for (int s = t; s < KNB*16; s += 128) {
        int k = s >> 4, p = s & 15;
        if (p < 15) {
            int a = c_PA[p], bb = c_PB[p];
            float dx = ia[a][0] - ja[k][bb][0];
            float dy = ia[a][1] - ja[k][bb][1];
            float dz = ia[a][2] - ja[k][bb][2];
            dist[k][p] = sqrtf(dx*dx + dy*dy + dz*dz + 1e-6f);
        }
    }
    __syncthreads();

    // 16 RBF banks x 16 mus: Fsm[k][16 + p*16 + m]
    for (int s = t; s < KNB*256; s += 128) {
        int k = s >> 8, r = s & 255, p = r >> 4, m = r & 15;
        float d  = (p == 0) ? dsel[k] : dist[k][p-1];
        float mu = 2.0f + (float)m * (20.0f/15.0f);
        float z  = (d - mu) * 0.8f;          // 1/sigma = 16/20
        Fsm[k][16 + r] = __expf(-z*z);
    }
    __syncthreads();

    // ---- GEMM: acc[k] = sum_c Fsm[k][c] * W_edge[c][t] ----
    float acc[KNB];
    #pragma unroll
    for (int k = 0; k < KNB; k++) acc[k] = 0.f;

    for (int c = 0; c < NF; c += 4) {
        float w0 = W_edge[(c+0)*NOUT + t];
        float w1 = W_edge[(c+1)*NOUT + t];
        float w2 = W_edge[(c+2)*NOUT + t];
        float w3 = W_edge[(c+3)*NOUT + t];
        #pragma unroll
        for (int k = 0; k < KNB; k++) {
            float4 f = *reinterpret_cast<const float4*>(&Fsm[k][c]);
            acc[k] = fmaf(f.x, w0, acc[k]);
            acc[k] = fmaf(f.y, w1, acc[k]);
            acc[k] = fmaf(f.z, w2, acc[k]);
            acc[k] = fmaf(f.w, w3, acc[k]);
        }
    }

    // ---- layernorm over the 128 columns (one element per thread) ----
    int warp = t >> 5, lane = t & 31;
    #pragma unroll
    for (int k = 0; k < KNB; k++) {
        float s = acc[k], q = acc[k]*acc[k];
        #pragma unroll
        for (int o = 16; o > 0; o >>= 1) {
            s += __shfl_xor_sync(0xffffffffu, s, o);
            q += __shfl_xor_sync(0xffffffffu, q, o);
        }
        if (lane == 0) { psum[warp][k] = s; psq[warp][k] = q; }
    }
    __syncthreads();

    float g  = gamma[t];
    float be = beta[t];
    #pragma unroll
    for (int k = 0; k < KNB; k++) {
        float s  = psum[0][k] + psum[1][k] + psum[2][k] + psum[3][k];
        float q  = psq [0][k] + psq [1][k] + psq [2][k] + psq [3][k];
        float mu  = s * (1.0f/NOUT);
        float var = fmaxf(q * (1.0f/NOUT) - mu*mu, 0.0f);
        float inv = rsqrtf(var + 1e-5f);
        outE[(row*KNB + k)*NOUT + t] = (acc[k] - mu)*inv*g + be;
    }
}

// ============================================================
extern "C" void kernel_launch(void* const* d_in, const int* in_sizes, int n_in,
                              void* d_out, int out_size)
{
    const float* X      = (const float*)d_in[0];
    const float* mask   = (const float*)d_in[1];
    const int*   ridx   = (const int*)  d_in[2];
    const int*   chain  = (const int*)  d_in[3];
    const float* W_pos  = (const float*)d_in[4];
    const float* b_pos  = (const float*)d_in[5];
    const float* W_edge = (const float*)d_in[6];
    const float* gamma  = (const float*)d_in[7];
    const float* beta   = (const float*)d_in[8];

    float* outE = (float*)d_out;
    long long esz = (long long)BSZ*LSZ*KNB*NOUT;     // 31,457,280
    // tuple output (E, E_idx): E_idx follows E, cast to the output dtype (f32)
    float* outIdxF = ((long long)out_size > esz) ? (outE + esz) : nullptr;

    cb_kernel  <<<(BSZ*LSZ + 255)/256, 256>>>(X);
    topk_kernel<<<BSZ*LSZ, 256>>>(X, mask, outIdxF);
    edge_kernel<<<BSZ*LSZ, 128>>>(X, ridx, chain, W_pos, b_pos, W_edge,
                                  gamma, beta, outE);
}

// round 5
// speedup vs baseline: 1.0012x; 1.0012x over previous
#include <cuda_runtime.h>
#include <cuda_bf16.h>
#include <cstdint>

// Problem constants (shapes fixed by setup_inputs)
#define BSZ   4
#define LSZ   2048
#define KNB   30      // TOP_K
#define NRBF  16
#define NF    272     // 16 positional + 16 banks * 16 rbf
#define NOUT  128
#define MAXREL 32

// -------- device scratch (no cudaMalloc allowed) --------
__device__ float g_Cb  [BSZ*LSZ*3];
__device__ int   g_Eidx[BSZ*LSZ*KNB];
__device__ float g_Dsel[BSZ*LSZ*KNB];

// pair tables: dist(A_atom of residue i, B_atom of residue j)
// atom codes: 0=N (X[...,0]), 1=C (X[...,1]), 2=Ca (X[...,2]), 3=Cb (virtual)
__constant__ int c_PA[15] = {0,2,3,1,1,1,0,0,3,0,2,3,2,3,2};
__constant__ int c_PB[15] = {0,2,3,0,2,3,2,3,2,1,1,1,0,0,3};

// ============================================================
// Kernel 1: virtual C-beta per residue
// ============================================================
__global__ void cb_kernel(const float* __restrict__ X)
{
    int i = blockIdx.x * 256 + threadIdx.x;
    if (i >= BSZ*LSZ) return;
    const float* x = &X[i*12];
    float Nx=x[0],  Ny=x[1],  Nz=x[2];   // N  = X[:,:,0]
    float Cx=x[3],  Cy=x[4],  Cz=x[5];   // C  = X[:,:,1]
    float Ax=x[6],  Ay=x[7],  Az=x[8];   // Ca = X[:,:,2]
    float bx=Ax-Nx, by=Ay-Ny, bz=Az-Nz;          // b = Ca - N
    float cx=Cx-Ax, cy=Cy-Ay, cz=Cz-Az;          // c = C - Ca
    float ax = by*cz - bz*cy;                    // a = cross(b,c)
    float ay = bz*cx - bx*cz;
    float az = bx*cy - by*cx;
    g_Cb[i*3+0] = -0.58273431f*ax + 0.56802827f*bx - 0.54067466f*cx + Ax;
    g_Cb[i*3+1] = -0.58273431f*ay + 0.56802827f*by - 0.54067466f*cy + Ay;
    g_Cb[i*3+2] = -0.58273431f*az + 0.56802827f*bz - 0.54067466f*cz + Az;
}

// ============================================================
// Kernel 2: masked pairwise C-C distances + exact top-30
// key = (float_bits << 32) | j  -> min gives ascending distance,
// ties broken by lower index == jax.lax.top_k stable order.
// ============================================================
__global__ __launch_bounds__(256) void topk_kernel(
    const float* __restrict__ X, const float* __restrict__ mask,
    float* __restrict__ outIdxF)
{
    int row = blockIdx.x;           // b*L + i
    int b   = row / LSZ;
    int t   = threadIdx.x;

    __shared__ float sD[LSZ];
    __shared__ float wmax[8];
    __shared__ unsigned long long wmin[8];
    __shared__ float sDmax;

    float cx = X[row*12+3], cy = X[row*12+4], cz = X[row*12+5];  // C atom
    float mi = mask[row];

    float lmax = 0.f;
    for (int j = t; j < LSZ; j += 256) {
        const float* xj = &X[(b*LSZ + j)*12 + 3];
        float dx = cx-xj[0], dy = cy-xj[1], dz = cz-xj[2];
        float d  = sqrtf(dx*dx + dy*dy + dz*dz + 1e-6f);
        float md = mi * mask[b*LSZ + j] * d;
        sD[j] = md;
        lmax = fmaxf(lmax, md);
    }
    #pragma unroll
    for (int o = 16; o > 0; o >>= 1) lmax = fmaxf(lmax, __shfl_xor_sync(0xffffffffu, lmax, o));
    if ((t & 31) == 0) wmax[t >> 5] = lmax;
    __syncthreads();
    if (t == 0) {
        float m = wmax[0];
        for (int w = 1; w < 8; w++) m = fmaxf(m, wmax[w]);
        sDmax = m;
    }
    __syncthreads();
    float Dmax = sDmax;
    for (int j = t; j < LSZ; j += 256) {
        float m2 = mi * mask[b*LSZ + j];
        sD[j] += (1.0f - m2) * Dmax;     // D_adjust
    }
    __syncthreads();

    for (int it = 0; it < KNB; it++) {
        unsigned long long best = ~0ull;
        #pragma unroll
        for (int r = 0; r < LSZ/256; r++) {
            int j = t + r*256;
            unsigned long long key =
                ((unsigned long long)__float_as_uint(sD[j]) << 32) | (unsigned)j;
            if (key < best) best = key;
        }
        #pragma unroll
        for (int o = 16; o > 0; o >>= 1) {
            unsigned long long oth = __shfl_xor_sync(0xffffffffu, best, o);
            if (oth < best) best = oth;
        }
        if ((t & 31) == 0) wmin[t >> 5] = best;
        __syncthreads();
        if (t == 0) {
            unsigned long long g = wmin[0];
            for (int w = 1; w < 8; w++) if (wmin[w] < g) g = wmin[w];
            int jm = (int)(unsigned)g;
            g_Eidx[row*KNB + it] = jm;
            g_Dsel[row*KNB + it] = __uint_as_float((unsigned)(g >> 32));
            if (outIdxF) outIdxF[row*KNB + it] = (float)jm;
            sD[jm] = __int_as_float(0x7f800000);   // +inf, remove from pool
        }
        __syncthreads();
    }
}

// ============================================================
// Kernel 3: fused edge features (positional + 16 RBF banks)
//           -> 272x128 projection -> layernorm
// One block per (b,i) row; 128 threads = one output column each,
// acc[30] register tile over the 30 neighbors.
// ============================================================
__global__ __launch_bounds__(128, 4) void edge_kernel(
    const float* __restrict__ X,
    const int*   __restrict__ ridx,
    const int*   __restrict__ chain,
    const float* __restrict__ W_pos,
    const float* __restrict__ b_pos,
    const float* __restrict__ W_edge,
    const float* __restrict__ gamma,
    const float* __restrict__ beta,
    float*       __restrict__ outE)
{
    int row = blockIdx.x;           // b*L + i
    int b   = row / LSZ;
    int t   = threadIdx.x;

    __shared__ float Fsm[KNB][NF];        // 30 x 272 feature tile
    __shared__ float ia[4][3];            // i atoms: N,C,Ca,Cb
    __shared__ float ja[KNB][4][3];       // j atoms per neighbor
    __shared__ int   jidx[KNB];
    __shared__ float dsel[KNB];
    __shared__ float dist[KNB][15];
    __shared__ float psum[4][KNB];
    __shared__ float psq [4][KNB];

    // stage neighbor list + i atoms
    if (t < KNB) { jidx[t] = g_Eidx[row*KNB + t]; dsel[t] = g_Dsel[row*KNB + t]; }
    if (t >= 32 && t < 41) { int r = t - 32; ia[r/3][r%3] = X[row*12 + r]; }
    if (t >= 64 && t < 67) { ia[3][t-64] = g_Cb[row*3 + (t-64)]; }
    __syncthreads();

    // stage j atoms (N,C,Ca from X; Cb virtual)
    for (int s = t; s < KNB*12; s += 128) {
        int k = s / 12, r = s % 12;
        int j = jidx[k];
        if (r < 9) ja[k][r/3][r%3] = X[(b*LSZ + j)*12 + r];
        else       ja[k][3][r-9]   = g_Cb[(b*LSZ + j)*3 + (r-9)];
    }

    // positional features: Fsm[k][0..15] = W_pos[d] + b_pos
    int my_ri = ridx[row];
    int my_ch = chain[row];
    for (int s = t; s < KNB*16; s += 128) {
        int k = s >> 4, f = s & 15;
        int j = jidx[k];
        int off  = my_ri - ridx[b*LSZ + j];
        int same = (my_ch == chain[b*LSZ + j]);
        int dcode = same ? min(max(off + MAXREL, 0), 2*MAXREL) : (2*MAXREL + 1);
        Fsm[k][f] = W_pos[dcode*16 + f] + b_pos[f];
    }
    __syncthreads();

    // 15 pair distances per edge
    for (int s = t; s < KNB*16; s += 128) {
        int k = s >> 4, p = s & 15;
        if (p < 15) {
            int a = c_PA[p], bb = c_PB[p];
            float dx = ia[a][0] - ja[k][bb][0];
            float dy = ia[a][1] - ja[k][bb][1];
            float dz = ia[a][2] - ja[k][bb][2];
            dist[k][p] = sqrtf(dx*dx + dy*dy + dz*dz + 1e-6f);
        }
    }
    __syncthreads();

    // 16 RBF banks x 16 mus: Fsm[k][16 + p*16 + m]
    for (int s = t; s < KNB*256; s += 128) {
        int k = s >> 8, r = s & 255, p = r >> 4, m = r & 15;
        float d  = (p == 0) ? dsel[k] : dist[k][p-1];
        float mu = 2.0f + (float)m * (20.0f/15.0f);
        float z  = (d - mu) * 0.8f;          // 1/sigma = 16/20
        Fsm[k][16 + r] = __expf(-z*z);
    }
    __syncthreads();

    // ---- GEMM: acc[k] = sum_c Fsm[k][c] * W_edge[c][t] ----
    float acc[KNB];
    #pragma unroll
    for (int k = 0; k < KNB; k++) acc[k] = 0.f;

    for (int c = 0; c < NF; c += 4) {
        float w0 = W_edge[(c+0)*NOUT + t];
        float w1 = W_edge[(c+1)*NOUT + t];
        float w2 = W_edge[(c+2)*NOUT + t];
        float w3 = W_edge[(c+3)*NOUT + t];
        #pragma unroll
        for (int k = 0; k < KNB; k++) {
            float4 f = *reinterpret_cast<const float4*>(&Fsm[k][c]);
            acc[k] = fmaf(f.x, w0, acc[k]);
            acc[k] = fmaf(f.y, w1, acc[k]);
            acc[k] = fmaf(f.z, w2, acc[k]);
            acc[k] = fmaf(f.w, w3, acc[k]);
        }
    }

    // ---- layernorm over the 128 columns (one element per thread) ----
    int warp = t >> 5, lane = t & 31;
    #pragma unroll
    for (int k = 0; k < KNB; k++) {
        float s = acc[k], q = acc[k]*acc[k];
        #pragma unroll
        for (int o = 16; o > 0; o >>= 1) {
            s += __shfl_xor_sync(0xffffffffu, s, o);
            q += __shfl_xor_sync(0xffffffffu, q, o);
        }
        if (lane == 0) { psum[warp][k] = s; psq[warp][k] = q; }
    }
    __syncthreads();

    float g  = gamma[t];
    float be = beta[t];
    #pragma unroll
    for (int k = 0; k < KNB; k++) {
        float s  = psum[0][k] + psum[1][k] + psum[2][k] + psum[3][k];
        float q  = psq [0][k] + psq [1][k] + psq [2][k] + psq [3][k];
        float mu  = s * (1.0f/NOUT);
        float var = fmaxf(q * (1.0f/NOUT) - mu*mu, 0.0f);
        float inv = rsqrtf(var + 1e-5f);
        outE[(row*KNB + k)*NOUT + t] = (acc[k] - mu)*inv*g + be;
    }
}

// ============================================================
extern "C" void kernel_launch(void* const* d_in, const int* in_sizes, int n_in,
                              void* d_out, int out_size)
{
    const float* X      = (const float*)d_in[0];
    const float* mask   = (const float*)d_in[1];
    const int*   ridx   = (const int*)  d_in[2];
    const int*   chain  = (const int*)  d_in[3];
    const float* W_pos  = (const float*)d_in[4];
    const float* b_pos  = (const float*)d_in[5];
    const float* W_edge = (const float*)d_in[6];
    const float* gamma  = (const float*)d_in[7];
    const float* beta   = (const float*)d_in[8];

    float* outE = (float*)d_out;
    long long esz = (long long)BSZ*LSZ*KNB*NOUT;     // 31,457,280
    // tuple output (E, E_idx): E_idx follows E, cast to the output dtype (f32)
    float* outIdxF = ((long long)out_size > esz) ? (outE + esz) : nullptr;

    cb_kernel  <<<(BSZ*LSZ + 255)/256, 256>>>(X);
    topk_kernel<<<BSZ*LSZ, 256>>>(X, mask, outIdxF);
    edge_kernel<<<BSZ*LSZ, 128>>>(X, ridx, chain, W_pos, b_pos, W_edge,
                                  gamma, beta, outE);
}